// round 5
// baseline (speedup 1.0000x reference)
#include <cuda_runtime.h>
#include <cuda_bf16.h>
#include <stdint.h>
#include <math.h>

#define B_   32
#define C_   256
#define HH   56
#define WW   56
#define E_   4
#define O_   256
#define HID_ 64
#define NPIX 3136
#define KDIM 2304
#define WPERB (O_*KDIM)
#define BK   32
#define PADK 36                       // padded k-stride (floats); 144B rows
#define NKT  (KDIM/BK)                // 72 k-tiles
#define ASTAGE (256*PADK)             // floats per A stage
#define BSTAGE (128*PADK)             // floats per B stage

// ---------------- device scratch (no runtime allocation) ----------------
__device__ float g_routing[B_*E_];
__device__ float g_pooled[B_*C_];
__device__ float g_combined[(size_t)B_*WPERB];   // tf32-rounded mixed weights

// ---------------- helpers ----------------
__device__ __forceinline__ uint32_t f2tf32(float f) {
    uint32_t u;
    asm("cvt.rna.tf32.f32 %0, %1;" : "=r"(u) : "f"(f));
    return u;
}

__device__ __forceinline__ void mma_tf32(float* d, const uint32_t* a, const uint32_t* b) {
    asm volatile(
        "mma.sync.aligned.m16n8k8.row.col.f32.tf32.tf32.f32 "
        "{%0,%1,%2,%3}, {%4,%5,%6,%7}, {%8,%9}, {%0,%1,%2,%3};"
        : "+f"(d[0]), "+f"(d[1]), "+f"(d[2]), "+f"(d[3])
        : "r"(a[0]), "r"(a[1]), "r"(a[2]), "r"(a[3]), "r"(b[0]), "r"(b[1]));
}

#define CP_ASYNC16(dst_u32, src_ptr) \
    asm volatile("cp.async.cg.shared.global [%0], [%1], 16;" :: "r"(dst_u32), "l"(src_ptr))
#define CP_COMMIT() asm volatile("cp.async.commit_group;" ::: "memory")
#define CP_WAIT0()  asm volatile("cp.async.wait_group 0;"  ::: "memory")
#define CP_WAIT1()  asm volatile("cp.async.wait_group 1;"  ::: "memory")

// ===========================================================================
// Kernel 1a: per-channel global average pool. grid (C_, B_), 128 threads.
// ===========================================================================
__global__ void __launch_bounds__(128) pool_kernel(const float* __restrict__ x) {
    const int c = blockIdx.x, b = blockIdx.y;
    const int tid = threadIdx.x;
    const float4* xc = (const float4*)(x + ((size_t)b*C_ + c)*NPIX);
    float s = 0.f;
    for (int i = tid; i < NPIX/4; i += 128) { float4 v = xc[i]; s += (v.x+v.y)+(v.z+v.w); }
    #pragma unroll
    for (int o = 16; o; o >>= 1) s += __shfl_xor_sync(0xffffffffu, s, o);
    __shared__ float ws[4];
    if ((tid & 31) == 0) ws[tid >> 5] = s;
    __syncthreads();
    if (tid == 0) g_pooled[b*C_ + c] = (ws[0]+ws[1]+ws[2]+ws[3]) * (1.0f/(float)NPIX);
}

// ===========================================================================
// Kernel 1b: MLP + softmax routing. grid B_, 64 threads.
// ===========================================================================
__global__ void __launch_bounds__(64) mlp_kernel(const float* __restrict__ rw1,
                                                 const float* __restrict__ rb1,
                                                 const float* __restrict__ rw2,
                                                 const float* __restrict__ rb2) {
    const int b = blockIdx.x, t = threadIdx.x;
    __shared__ float pl[C_];
    __shared__ float hid[HID_];
    __shared__ float logits[E_];
    for (int c = t; c < C_; c += 64) pl[c] = g_pooled[b*C_ + c];
    __syncthreads();
    {
        float s = rb1[t];
        const float* w = rw1 + t * C_;
        #pragma unroll 8
        for (int c = 0; c < C_; c++) s = fmaf(w[c], pl[c], s);
        hid[t] = fmaxf(s, 0.f);
    }
    __syncthreads();
    if (t < E_) {
        float s = rb2[t];
        const float* w = rw2 + t * HID_;
        #pragma unroll 8
        for (int h = 0; h < HID_; h++) s = fmaf(w[h], hid[h], s);
        logits[t] = s;
    }
    __syncthreads();
    if (t == 0) {
        float m = logits[0];
        #pragma unroll
        for (int e = 1; e < E_; e++) m = fmaxf(m, logits[e]);
        float ex[E_], sum = 0.f;
        #pragma unroll
        for (int e = 0; e < E_; e++) { ex[e] = expf(logits[e] - m); sum += ex[e]; }
        float inv = 1.0f / sum;
        #pragma unroll
        for (int e = 0; e < E_; e++) g_routing[b*E_ + e] = ex[e] * inv;
    }
}

// ===========================================================================
// Kernel 2: mix experts -> per-sample weights (tf32-rounded fp32).
// ===========================================================================
__global__ void __launch_bounds__(256) combine_kernel(const float* __restrict__ experts) {
    const int b = blockIdx.y;
    const int i = blockIdx.x * 256 + threadIdx.x;     // float4 index
    if (i >= WPERB/4) return;

    const float r0 = g_routing[b*E_+0], r1 = g_routing[b*E_+1];
    const float r2 = g_routing[b*E_+2], r3 = g_routing[b*E_+3];
    float4 a = ((const float4*)(experts + (size_t)0*WPERB))[i];
    float4 c = ((const float4*)(experts + (size_t)1*WPERB))[i];
    float4 d = ((const float4*)(experts + (size_t)2*WPERB))[i];
    float4 f = ((const float4*)(experts + (size_t)3*WPERB))[i];

    uint4 o;
    o.x = f2tf32(r0*a.x + r1*c.x + r2*d.x + r3*f.x);
    o.y = f2tf32(r0*a.y + r1*c.y + r2*d.y + r3*f.y);
    o.z = f2tf32(r0*a.z + r1*c.z + r2*d.z + r3*f.z);
    o.w = f2tf32(r0*a.w + r1*c.w + r2*d.w + r3*f.w);
    ((uint4*)g_combined)[(size_t)b*(WPERB/4) + i] = o;
}

// ===========================================================================
// Kernel 3: TF32 mma.sync implicit-GEMM conv, 3-stage pipeline.
//   CTA tile: 256(oc) x 128(px), K=2304 in 72 tiles of 32.
//   8 warps = 4(m) x 2(n); warp tile 64x64.
//   A: cp.async 2 tiles ahead (wait_group 1); B: LDG->reg->STS.128 mid-compute.
// ===========================================================================
__global__ void __launch_bounds__(256, 1) conv_mma_kernel(const float* __restrict__ x,
                                                          float* __restrict__ out) {
    extern __shared__ float sm[];
    float* As   = sm;                          // 3 * ASTAGE
    float* Bs   = sm + 3*ASTAGE;               // 3 * BSTAGE
    int2*  ktab = (int2*)(sm + 3*ASTAGE + 3*BSTAGE);

    const int tid   = threadIdx.x;
    const int lane  = tid & 31;
    const int warp  = tid >> 5;
    const int nBase = blockIdx.x * 128;
    const int b     = blockIdx.y;

    const int g  = lane >> 2;      // 0..7
    const int tg = lane & 3;       // 0..3
    const int wm = warp >> 1;      // 0..3 (m)
    const int wn = warp & 1;       // 0..1 (n)

    // im2col k-table: (gmem offset, tap index 0..8)
    for (int k = tid; k < KDIM; k += 256) {
        int c = k / 9, rem = k - 9*c;
        int ky = rem / 3 - 1, kx = rem % 3 - 1;
        ktab[k] = make_int2(c*NPIX + ky*WW + kx, (ky+1)*3 + (kx+1));
    }
    __syncthreads();

    const float* Ab = g_combined + (size_t)b * WPERB;
    const float* xb = x + (size_t)b * C_ * NPIX;

    // B producer: thread -> pixel nl, k-half kh (16 consecutive k each)
    const int nl = tid & 127;
    const int kh = tid >> 7;              // 0 or 1
    const int n  = nBase + nl;
    const int ny = n / WW, nx = n - (n / WW) * WW;

    // 9-bit per-thread validity mask over the 3x3 taps
    uint32_t vmask = 0;
    if (n < NPIX) {
        #pragma unroll
        for (int dy = -1; dy <= 1; dy++)
            #pragma unroll
            for (int dx = -1; dx <= 1; dx++)
                if ((unsigned)(ny+dy) < 56u && (unsigned)(nx+dx) < 56u)
                    vmask |= 1u << ((dy+1)*3 + (dx+1));
    }

    const uint32_t as_u32 = (uint32_t)__cvta_generic_to_shared(As);

    uint32_t breg[16];

    #define ISSUE_A(kt, s) do {                                                      \
        const int _k0 = (kt) * BK;                                                   \
        _Pragma("unroll")                                                            \
        for (int i = 0; i < 8; i++) {                                                \
            int idx = tid + i*256, row = idx >> 3, c4 = idx & 7;                     \
            uint32_t dst = as_u32 + (uint32_t)((s)*ASTAGE + row*PADK + c4*4)*4u;     \
            CP_ASYNC16(dst, Ab + (size_t)row*KDIM + _k0 + c4*4);                     \
        }                                                                            \
        CP_COMMIT();                                                                 \
    } while (0)

    #define LDG_B(kt) do {                                                           \
        const int _k0 = (kt) * BK + kh*16;                                           \
        _Pragma("unroll")                                                            \
        for (int i = 0; i < 16; i++) {                                               \
            int2 t = ktab[_k0 + i];                                                  \
            float v = 0.f;                                                           \
            if ((vmask >> t.y) & 1u) v = __ldg(xb + t.x + n);                        \
            breg[i] = f2tf32(v);                                                     \
        }                                                                            \
    } while (0)

    #define STS_B(s) do {                                                            \
        uint32_t* _d = (uint32_t*)(Bs + (s)*BSTAGE + nl*PADK + kh*16);               \
        _Pragma("unroll")                                                            \
        for (int i = 0; i < 4; i++)                                                  \
            *(uint4*)(_d + i*4) = make_uint4(breg[i*4], breg[i*4+1],                 \
                                             breg[i*4+2], breg[i*4+3]);              \
    } while (0)

    #define COMPUTE_KS(ks) do {                                                      \
        const int kc = (ks)*8 + tg;                                                  \
        uint32_t afr[4][4];                                                          \
        _Pragma("unroll")                                                            \
        for (int mi = 0; mi < 4; mi++) {                                             \
            const uint32_t* p = Aw + mi*16*PADK + kc;                                \
            afr[mi][0] = p[0];                                                       \
            afr[mi][1] = p[8*PADK];                                                  \
            afr[mi][2] = p[4];                                                       \
            afr[mi][3] = p[8*PADK + 4];                                              \
        }                                                                            \
        uint32_t bfr[8][2];                                                          \
        _Pragma("unroll")                                                            \
        for (int ni = 0; ni < 8; ni++) {                                             \
            const uint32_t* q = Bw + ni*8*PADK + kc;                                 \
            bfr[ni][0] = q[0];                                                       \
            bfr[ni][1] = q[4];                                                       \
        }                                                                            \
        _Pragma("unroll")                                                            \
        for (int mi = 0; mi < 4; mi++)                                               \
            _Pragma("unroll")                                                        \
            for (int ni = 0; ni < 8; ni++)                                           \
                mma_tf32(acc[mi][ni], afr[mi], bfr[ni]);                             \
    } while (0)

    float acc[4][8][4];
    #pragma unroll
    for (int mi = 0; mi < 4; mi++)
        #pragma unroll
        for (int ni = 0; ni < 8; ni++)
            #pragma unroll
            for (int q = 0; q < 4; q++) acc[mi][ni][q] = 0.f;

    // ---- prologue: A(0), A(1) in flight; B(0) in smem ----
    ISSUE_A(0, 0);
    ISSUE_A(1, 1);
    LDG_B(0);
    CP_WAIT1();            // A(0) landed
    STS_B(0);
    __syncthreads();

    int sA = 0;            // stage of current tile
    for (int kt = 0; kt < NKT; kt++) {
        const int sNext = (sA == 2) ? 0 : sA + 1;
        const int sPrev = (sA == 0) ? 2 : sA - 1;   // stage for tile kt+2

        if (kt + 2 < NKT) ISSUE_A(kt + 2, sPrev);
        if (kt + 1 < NKT) LDG_B(kt + 1);

        const uint32_t* Aw = (const uint32_t*)(As + sA*ASTAGE + (wm*64 + g)*PADK);
        const uint32_t* Bw = (const uint32_t*)(Bs + sA*BSTAGE + (wn*64 + g)*PADK);

        COMPUTE_KS(0);
        COMPUTE_KS(1);

        if (kt + 1 < NKT) STS_B(sNext);   // stage sNext idle since barrier kt-1

        COMPUTE_KS(2);
        COMPUTE_KS(3);

        if (kt + 1 < NKT) {
            if (kt + 2 < NKT) { CP_WAIT1(); }   // A(kt+1) landed, A(kt+2) may fly
            else              { CP_WAIT0(); }   // drain last A
            __syncthreads();
        }
        sA = sNext;
    }

    // ---- epilogue ----
    float* ob = out + (size_t)b * O_ * NPIX;
    #pragma unroll
    for (int mi = 0; mi < 4; mi++) {
        const int r0 = wm*64 + mi*16 + g;
        #pragma unroll
        for (int ni = 0; ni < 8; ni++) {
            const int cb = nBase + wn*64 + ni*8 + 2*tg;
            if (cb < NPIX) {
                *(float2*)(ob + (size_t)r0*NPIX + cb)     = make_float2(acc[mi][ni][0], acc[mi][ni][1]);
                *(float2*)(ob + (size_t)(r0+8)*NPIX + cb) = make_float2(acc[mi][ni][2], acc[mi][ni][3]);
            }
        }
    }
    #undef ISSUE_A
    #undef LDG_B
    #undef STS_B
    #undef COMPUTE_KS
}

#define CONV_SMEM ((3*ASTAGE + 3*BSTAGE)*4 + KDIM*8)   // 165888 + 18432 = 184320 B

// ===========================================================================
extern "C" void kernel_launch(void* const* d_in, const int* in_sizes, int n_in,
                              void* d_out, int out_size) {
    const float* x       = (const float*)d_in[0];
    const float* experts = (const float*)d_in[1];
    const float* rw1     = (const float*)d_in[2];
    const float* rb1     = (const float*)d_in[3];
    const float* rw2     = (const float*)d_in[4];
    const float* rb2     = (const float*)d_in[5];
    float* out           = (float*)d_out;

    static bool attr_set = false;
    if (!attr_set) {
        cudaFuncSetAttribute(conv_mma_kernel,
                             cudaFuncAttributeMaxDynamicSharedMemorySize, CONV_SMEM);
        attr_set = true;
    }

    pool_kernel<<<dim3(C_, B_), 128>>>(x);
    mlp_kernel<<<B_, 64>>>(rw1, rb1, rw2, rb2);
    combine_kernel<<<dim3((WPERB/4 + 255)/256, B_), 256>>>(experts);
    conv_mma_kernel<<<dim3(25, B_), 256, CONV_SMEM>>>(x, out);
}

// round 6
// speedup vs baseline: 1.2011x; 1.2011x over previous
#include <cuda_runtime.h>
#include <cuda_bf16.h>
#include <stdint.h>
#include <math.h>

#define B_   32
#define C_   256
#define HH   56
#define WW   56
#define E_   4
#define O_   256
#define HID_ 64
#define NPIX 3136
#define KDIM 2304
#define WPERB (O_*KDIM)
#define BK   32
#define PADK 36                       // padded k-stride (floats); 144B rows
#define NKT  (KDIM/BK)                // 72 k-tiles
#define MT   128                      // CTA m tile
#define NTL  128                      // CTA n tile
#define ASTG (MT*PADK)                // floats per A stage
#define BSTG (NTL*PADK)               // floats per B stage

// ---------------- device scratch (no runtime allocation) ----------------
__device__ float g_routing[B_*E_];
__device__ float g_pooled[B_*C_];
__device__ float g_combined[(size_t)B_*WPERB];   // tf32-rounded mixed weights

// ---------------- helpers ----------------
__device__ __forceinline__ uint32_t f2tf32(float f) {
    uint32_t u;
    asm("cvt.rna.tf32.f32 %0, %1;" : "=r"(u) : "f"(f));
    return u;
}

__device__ __forceinline__ void mma_tf32(float* d, const uint32_t* a, const uint32_t* b) {
    asm volatile(
        "mma.sync.aligned.m16n8k8.row.col.f32.tf32.tf32.f32 "
        "{%0,%1,%2,%3}, {%4,%5,%6,%7}, {%8,%9}, {%0,%1,%2,%3};"
        : "+f"(d[0]), "+f"(d[1]), "+f"(d[2]), "+f"(d[3])
        : "r"(a[0]), "r"(a[1]), "r"(a[2]), "r"(a[3]), "r"(b[0]), "r"(b[1]));
}

#define CP_ASYNC16(dst_u32, src_ptr) \
    asm volatile("cp.async.cg.shared.global [%0], [%1], 16;" :: "r"(dst_u32), "l"(src_ptr))
#define CP_COMMIT() asm volatile("cp.async.commit_group;" ::: "memory")
#define CP_WAIT0()  asm volatile("cp.async.wait_group 0;"  ::: "memory")

// ===========================================================================
// Kernel 1a: per-channel global average pool. grid (C_, B_), 128 threads.
// ===========================================================================
__global__ void __launch_bounds__(128) pool_kernel(const float* __restrict__ x) {
    const int c = blockIdx.x, b = blockIdx.y;
    const int tid = threadIdx.x;
    const float4* xc = (const float4*)(x + ((size_t)b*C_ + c)*NPIX);
    float s = 0.f;
    for (int i = tid; i < NPIX/4; i += 128) { float4 v = xc[i]; s += (v.x+v.y)+(v.z+v.w); }
    #pragma unroll
    for (int o = 16; o; o >>= 1) s += __shfl_xor_sync(0xffffffffu, s, o);
    __shared__ float ws[4];
    if ((tid & 31) == 0) ws[tid >> 5] = s;
    __syncthreads();
    if (tid == 0) g_pooled[b*C_ + c] = (ws[0]+ws[1]+ws[2]+ws[3]) * (1.0f/(float)NPIX);
}

// ===========================================================================
// Kernel 1b: MLP + softmax routing. grid B_, 64 threads.
// ===========================================================================
__global__ void __launch_bounds__(64) mlp_kernel(const float* __restrict__ rw1,
                                                 const float* __restrict__ rb1,
                                                 const float* __restrict__ rw2,
                                                 const float* __restrict__ rb2) {
    const int b = blockIdx.x, t = threadIdx.x;
    __shared__ float pl[C_];
    __shared__ float hid[HID_];
    __shared__ float logits[E_];
    for (int c = t; c < C_; c += 64) pl[c] = g_pooled[b*C_ + c];
    __syncthreads();
    {
        float s = rb1[t];
        const float* w = rw1 + t * C_;
        #pragma unroll 8
        for (int c = 0; c < C_; c++) s = fmaf(w[c], pl[c], s);
        hid[t] = fmaxf(s, 0.f);
    }
    __syncthreads();
    if (t < E_) {
        float s = rb2[t];
        const float* w = rw2 + t * HID_;
        #pragma unroll 8
        for (int h = 0; h < HID_; h++) s = fmaf(w[h], hid[h], s);
        logits[t] = s;
    }
    __syncthreads();
    if (t == 0) {
        float m = logits[0];
        #pragma unroll
        for (int e = 1; e < E_; e++) m = fmaxf(m, logits[e]);
        float ex[E_], sum = 0.f;
        #pragma unroll
        for (int e = 0; e < E_; e++) { ex[e] = expf(logits[e] - m); sum += ex[e]; }
        float inv = 1.0f / sum;
        #pragma unroll
        for (int e = 0; e < E_; e++) g_routing[b*E_ + e] = ex[e] * inv;
    }
}

// ===========================================================================
// Kernel 2: mix experts -> per-sample weights (tf32-rounded fp32).
// ===========================================================================
__global__ void __launch_bounds__(256) combine_kernel(const float* __restrict__ experts) {
    const int b = blockIdx.y;
    const int i = blockIdx.x * 256 + threadIdx.x;     // float4 index
    if (i >= WPERB/4) return;

    const float r0 = g_routing[b*E_+0], r1 = g_routing[b*E_+1];
    const float r2 = g_routing[b*E_+2], r3 = g_routing[b*E_+3];
    float4 a = ((const float4*)(experts + (size_t)0*WPERB))[i];
    float4 c = ((const float4*)(experts + (size_t)1*WPERB))[i];
    float4 d = ((const float4*)(experts + (size_t)2*WPERB))[i];
    float4 f = ((const float4*)(experts + (size_t)3*WPERB))[i];

    uint4 o;
    o.x = f2tf32(r0*a.x + r1*c.x + r2*d.x + r3*f.x);
    o.y = f2tf32(r0*a.y + r1*c.y + r2*d.y + r3*f.y);
    o.z = f2tf32(r0*a.z + r1*c.z + r2*d.z + r3*f.z);
    o.w = f2tf32(r0*a.w + r1*c.w + r2*d.w + r3*f.w);
    ((uint4*)g_combined)[(size_t)b*(WPERB/4) + i] = o;
}

// ===========================================================================
// Kernel 3: TF32 mma.sync implicit-GEMM conv, 2 CTAs/SM for latency hiding.
//   CTA tile: 128(oc) x 128(px), K=2304 in 72 tiles of 32.
//   8 warps = 2(m) x 4(n); warp tile 64x32 -> 64 acc regs/thread.
//   A: cp.async double-buffered; B: LDG->reg->STS.128 mid-compute.
// ===========================================================================
__global__ void __launch_bounds__(256, 2) conv_mma_kernel(const float* __restrict__ x,
                                                          float* __restrict__ out) {
    extern __shared__ float sm[];
    float* As   = sm;                          // 2 * ASTG
    float* Bs   = sm + 2*ASTG;                 // 2 * BSTG
    int2*  ktab = (int2*)(sm + 2*ASTG + 2*BSTG);

    const int tid   = threadIdx.x;
    const int lane  = tid & 31;
    const int warp  = tid >> 5;
    const int nBase = blockIdx.x * NTL;
    const int mBase = blockIdx.y * MT;
    const int b     = blockIdx.z;

    const int g  = lane >> 2;      // 0..7
    const int tg = lane & 3;       // 0..3
    const int wm = warp >> 2;      // 0..1 (m)
    const int wn = warp & 3;       // 0..3 (n)

    // im2col k-table: (gmem offset, tap index 0..8)
    for (int k = tid; k < KDIM; k += 256) {
        int c = k / 9, rem = k - 9*c;
        int ky = rem / 3 - 1, kx = rem % 3 - 1;
        ktab[k] = make_int2(c*NPIX + ky*WW + kx, (ky+1)*3 + (kx+1));
    }
    __syncthreads();

    const float* Ab = g_combined + (size_t)b * WPERB + (size_t)mBase * KDIM;
    const float* xb = x + (size_t)b * C_ * NPIX;

    // B producer: thread -> pixel nl, k-half kh (16 consecutive k each)
    const int nl = tid & 127;
    const int kh = tid >> 7;              // 0 or 1
    const int n  = nBase + nl;
    const int ny = n / WW, nx = n - (n / WW) * WW;

    // 9-bit per-thread validity mask over the 3x3 taps
    uint32_t vmask = 0;
    if (n < NPIX) {
        #pragma unroll
        for (int dy = -1; dy <= 1; dy++)
            #pragma unroll
            for (int dx = -1; dx <= 1; dx++)
                if ((unsigned)(ny+dy) < 56u && (unsigned)(nx+dx) < 56u)
                    vmask |= 1u << ((dy+1)*3 + (dx+1));
    }

    const uint32_t as_u32 = (uint32_t)__cvta_generic_to_shared(As);

    uint32_t breg[16];

    // A tile: 128 rows x 32 k = 1024 float4, 4 per thread
    #define ISSUE_A(kt, s) do {                                                      \
        const int _k0 = (kt) * BK;                                                   \
        _Pragma("unroll")                                                            \
        for (int i = 0; i < 4; i++) {                                                \
            int idx = tid + i*256, row = idx >> 3, c4 = idx & 7;                     \
            uint32_t dst = as_u32 + (uint32_t)((s)*ASTG + row*PADK + c4*4)*4u;       \
            CP_ASYNC16(dst, Ab + (size_t)row*KDIM + _k0 + c4*4);                     \
        }                                                                            \
        CP_COMMIT();                                                                 \
    } while (0)

    #define LDG_B(kt) do {                                                           \
        const int _k0 = (kt) * BK + kh*16;                                           \
        _Pragma("unroll")                                                            \
        for (int i = 0; i < 16; i++) {                                               \
            int2 t = ktab[_k0 + i];                                                  \
            float v = 0.f;                                                           \
            if ((vmask >> t.y) & 1u) v = __ldg(xb + t.x + n);                        \
            breg[i] = f2tf32(v);                                                     \
        }                                                                            \
    } while (0)

    #define STS_B(s) do {                                                            \
        uint32_t* _d = (uint32_t*)(Bs + (s)*BSTG + nl*PADK + kh*16);                 \
        _Pragma("unroll")                                                            \
        for (int i = 0; i < 4; i++)                                                  \
            *(uint4*)(_d + i*4) = make_uint4(breg[i*4], breg[i*4+1],                 \
                                             breg[i*4+2], breg[i*4+3]);              \
    } while (0)

    #define COMPUTE_KS(ks) do {                                                      \
        const int kc = (ks)*8 + tg;                                                  \
        uint32_t afr[4][4];                                                          \
        _Pragma("unroll")                                                            \
        for (int mi = 0; mi < 4; mi++) {                                             \
            const uint32_t* p = Aw + mi*16*PADK + kc;                                \
            afr[mi][0] = p[0];                                                       \
            afr[mi][1] = p[8*PADK];                                                  \
            afr[mi][2] = p[4];                                                       \
            afr[mi][3] = p[8*PADK + 4];                                              \
        }                                                                            \
        uint32_t bfr[4][2];                                                          \
        _Pragma("unroll")                                                            \
        for (int ni = 0; ni < 4; ni++) {                                             \
            const uint32_t* q = Bw + ni*8*PADK + kc;                                 \
            bfr[ni][0] = q[0];                                                       \
            bfr[ni][1] = q[4];                                                       \
        }                                                                            \
        _Pragma("unroll")                                                            \
        for (int mi = 0; mi < 4; mi++)                                               \
            _Pragma("unroll")                                                        \
            for (int ni = 0; ni < 4; ni++)                                           \
                mma_tf32(acc[mi][ni], afr[mi], bfr[ni]);                             \
    } while (0)

    float acc[4][4][4];
    #pragma unroll
    for (int mi = 0; mi < 4; mi++)
        #pragma unroll
        for (int ni = 0; ni < 4; ni++)
            #pragma unroll
            for (int q = 0; q < 4; q++) acc[mi][ni][q] = 0.f;

    // ---- prologue ----
    ISSUE_A(0, 0);
    LDG_B(0);
    CP_WAIT0();
    STS_B(0);
    __syncthreads();

    for (int kt = 0; kt < NKT; kt++) {
        const int cur = kt & 1;
        if (kt + 1 < NKT) {
            ISSUE_A(kt + 1, cur ^ 1);
            LDG_B(kt + 1);
        }

        const uint32_t* Aw = (const uint32_t*)(As + cur*ASTG + (wm*64 + g)*PADK);
        const uint32_t* Bw = (const uint32_t*)(Bs + cur*BSTG + (wn*32 + g)*PADK);

        COMPUTE_KS(0);
        COMPUTE_KS(1);

        if (kt + 1 < NKT) STS_B(cur ^ 1);   // other buffer idle since barrier kt-1

        COMPUTE_KS(2);
        COMPUTE_KS(3);

        if (kt + 1 < NKT) {
            CP_WAIT0();
            __syncthreads();
        }
    }

    // ---- epilogue ----
    float* ob = out + (size_t)b * O_ * NPIX;
    #pragma unroll
    for (int mi = 0; mi < 4; mi++) {
        const int r0 = mBase + wm*64 + mi*16 + g;
        #pragma unroll
        for (int ni = 0; ni < 4; ni++) {
            const int cb = nBase + wn*32 + ni*8 + 2*tg;
            if (cb < NPIX) {
                *(float2*)(ob + (size_t)r0*NPIX + cb)     = make_float2(acc[mi][ni][0], acc[mi][ni][1]);
                *(float2*)(ob + (size_t)(r0+8)*NPIX + cb) = make_float2(acc[mi][ni][2], acc[mi][ni][3]);
            }
        }
    }
    #undef ISSUE_A
    #undef LDG_B
    #undef STS_B
    #undef COMPUTE_KS
}

#define CONV_SMEM ((2*ASTG + 2*BSTG)*4 + KDIM*8)   // 73728 + 18432 = 92160 B

// ===========================================================================
extern "C" void kernel_launch(void* const* d_in, const int* in_sizes, int n_in,
                              void* d_out, int out_size) {
    const float* x       = (const float*)d_in[0];
    const float* experts = (const float*)d_in[1];
    const float* rw1     = (const float*)d_in[2];
    const float* rb1     = (const float*)d_in[3];
    const float* rw2     = (const float*)d_in[4];
    const float* rb2     = (const float*)d_in[5];
    float* out           = (float*)d_out;

    static bool attr_set = false;
    if (!attr_set) {
        cudaFuncSetAttribute(conv_mma_kernel,
                             cudaFuncAttributeMaxDynamicSharedMemorySize, CONV_SMEM);
        attr_set = true;
    }

    pool_kernel<<<dim3(C_, B_), 128>>>(x);
    mlp_kernel<<<B_, 64>>>(rw1, rb1, rw2, rb2);
    combine_kernel<<<dim3((WPERB/4 + 255)/256, B_), 256>>>(experts);
    conv_mma_kernel<<<dim3(25, 2, B_), 256, CONV_SMEM>>>(x, out);
}